// round 11
// baseline (speedup 1.0000x reference)
#include <cuda_runtime.h>
#include <cuda_fp16.h>
#include <cstdint>

#define KDIM 64
#define SDIM 512
#define TILE_M 64
#define NT 256
#define NCTAS 296           // 2 CTAs/SM x 148 SMs
#define NTILES 1024         // 65536 / 64
#define TAU 2.5e-3f
#define FLGMAX 256          // static stride -> max 4 tiles x 64 rows per CTA
#define INFF 3.4e38f

// smem byte offsets
#define OFF_BH   0          // 512 * 144 (fp16 hi of codebook, pitched)
#define OFF_AH   73728      // 64 * 144  (fp16 hi of -2*vecs tile)
#define OFF_CN   82944      // 512 * 4
#define OFF_VN   84992      // 64 * 4
#define OFF_KF   85248      // 2 * 64 * 4  best float   [ch][row]
#define OFF_KI   85760      // 2 * 64 * 4  best idx
#define OFF_SC   86272      // 2 * 64 * 4  second float
#define OFF_ZR   86784      // 64 * 4
#define OFF_RED  87040      // 64 * 4
#define OFF_FLG  87296      // FLGMAX * 4
#define OFF_CTL  88320      // fcnt
#define SMEM_TOTAL 88384

typedef unsigned long long ull;

__device__ float    g_tilesum[NTILES];
__device__ unsigned g_ticket;

__device__ __forceinline__ uint32_t smem_u32(const void* p) {
    uint32_t a;
    asm("{ .reg .u64 t; cvta.to.shared.u64 t, %1; cvt.u32.u64 %0, t; }" : "=r"(a) : "l"(p));
    return a;
}
__device__ __forceinline__ void ldsm4(uint32_t& r0, uint32_t& r1, uint32_t& r2, uint32_t& r3,
                                      uint32_t a) {
    asm volatile("ldmatrix.sync.aligned.m8n8.x4.shared.b16 {%0,%1,%2,%3}, [%4];"
                 : "=r"(r0), "=r"(r1), "=r"(r2), "=r"(r3) : "r"(a));
}
__device__ __forceinline__ void mma16816(float* d, const uint32_t* a,
                                         uint32_t b0, uint32_t b1) {
    asm volatile("mma.sync.aligned.m16n8k16.row.col.f32.f16.f16.f32 "
                 "{%0,%1,%2,%3}, {%4,%5,%6,%7}, {%8,%9}, {%0,%1,%2,%3};"
                 : "+f"(d[0]), "+f"(d[1]), "+f"(d[2]), "+f"(d[3])
                 : "r"(a[0]), "r"(a[1]), "r"(a[2]), "r"(a[3]), "r"(b0), "r"(b1));
}
struct R3 { float b, s; int i; };
__device__ __forceinline__ void mergeR(R3& a, const R3& o) {
    float ns = fminf(fminf(a.s, o.s), fmaxf(a.b, o.b));
    if (o.b < a.b) { a.b = o.b; a.i = o.i; }
    a.s = ns;
}
// branch-light best/second/idx update (validated R9/R10)
#define SCORE(v, sidx, lb, ls, li) do {            \
    float _v = (v);                                 \
    float _m = fmaxf(lb, _v);                       \
    ls = fminf(ls, _m);                             \
    bool _p = _v < lb;                              \
    lb = fminf(lb, _v);                             \
    li = _p ? (sidx) : li;                          \
} while (0)

// ---------------------------------------------------------------------------
// Single persistent kernel: fp16 hh-MMA screening + margin flags + inline
// exact cleanup + in-kernel loss reduction. 2 CTAs/SM. 32-col subchunks so
// the fully-hoisted live set fits in the 128-reg cap (no spills).
// ---------------------------------------------------------------------------
__global__ void __launch_bounds__(NT, 2)
vq_all(const float* __restrict__ vecs, const float* __restrict__ cb,
       float* __restrict__ out, int N, int ntiles, int nctas)
{
    extern __shared__ char smb[];
    float* cnsm   = (float*)(smb + OFF_CN);
    float* vn_s   = (float*)(smb + OFF_VN);
    float* keyf   = (float*)(smb + OFF_KF);
    int*   keyi   = (int*)(smb + OFF_KI);
    float* secf   = (float*)(smb + OFF_SC);
    int*   zrow   = (int*)(smb + OFF_ZR);
    float* redrow = (float*)(smb + OFF_RED);
    int*   flg    = (int*)(smb + OFF_FLG);
    int*   fcnt   = (int*)(smb + OFF_CTL);

    const int tid  = threadIdx.x;
    const int lane = tid & 31;
    const int wid  = tid >> 5;
    const int mb   = wid & 3;       // m16 block (4 per 64-row tile)
    const int ch   = wid >> 2;      // column half (2 x 256 codewords)
    const int col2 = (lane & 3) * 2;

    if (tid == 0) fcnt[0] = 0;

    // A-tile ownership: thread owns row=tid>>2, quarter aq=(tid&3) (16 floats)
    const int arow = tid >> 2;
    const int aq   = tid & 3;

    // ---- prologue: B hi-split -> smem, cn -> smem ----
    for (int n = tid; n < SDIM * (KDIM / 4); n += NT) {
        int row = n >> 4, q = n & 15;
        float4 v = __ldg((const float4*)(cb + (long)row * KDIM) + q);
        __half2 h01 = __floats2half2_rn(v.x, v.y);
        __half2 h23 = __floats2half2_rn(v.z, v.w);
        uint2 hp; hp.x = *(uint32_t*)&h01; hp.y = *(uint32_t*)&h23;
        *(uint2*)(smb + OFF_BH + row * 144 + q * 8) = hp;
    }
    #pragma unroll
    for (int r = 0; r < SDIM / NT; r++) {
        int s = r * NT + tid;
        const float4* row = (const float4*)(cb + (long)s * KDIM);
        float acc = 0.f;
        #pragma unroll
        for (int q = 0; q < KDIM / 4; q++) {
            float4 v = __ldg(row + q);
            acc = fmaf(v.x, v.x, acc);
            acc = fmaf(v.y, v.y, acc);
            acc = fmaf(v.z, v.z, acc);
            acc = fmaf(v.w, v.w, acc);
        }
        cnsm[s] = acc;
    }

    // ldmatrix lane address components (layout validated R6-R10)
    const uint32_t a_lane_off =
        ((lane & 7) + ((lane >> 3) & 1) * 8) * 144 + (lane >> 4) * 16;
    const uint32_t b_lane_off =
        ((lane & 7) + ((lane >> 4) & 1) * 8) * 144 + ((lane >> 3) & 1) * 16;
    const uint32_t ah_base = smem_u32(smb + OFF_AH) + mb * 2304 + a_lane_off;
    const uint32_t bh_base = smem_u32(smb + OFF_BH) + b_lane_off;

    float* out_z = out + (long)N * KDIM;

    for (int tile = blockIdx.x; tile < ntiles; tile += nctas) {
        // ---- load + split A tile (LDG -> fp16 hi of -2*a -> smem; vn) ----
        {
            const float4* src =
                (const float4*)(vecs + ((long)tile * TILE_M + arow) * KDIM) + aq * 4;
            float p = 0.f;
            uint32_t hx[8];
            #pragma unroll
            for (int j = 0; j < 4; j++) {
                float4 v = __ldg(src + j);
                p = fmaf(v.x, v.x, p); p = fmaf(v.y, v.y, p);
                p = fmaf(v.z, v.z, p); p = fmaf(v.w, v.w, p);
                __half2 a = __floats2half2_rn(-2.f * v.x, -2.f * v.y);
                __half2 b = __floats2half2_rn(-2.f * v.z, -2.f * v.w);
                hx[j * 2] = *(uint32_t*)&a; hx[j * 2 + 1] = *(uint32_t*)&b;
            }
            *(uint4*)(smb + OFF_AH + arow * 144 + aq * 32)      = *(uint4*)&hx[0];
            *(uint4*)(smb + OFF_AH + arow * 144 + aq * 32 + 16) = *(uint4*)&hx[4];
            p += __shfl_xor_sync(0xffffffffu, p, 1);
            p += __shfl_xor_sync(0xffffffffu, p, 2);
            if (aq == 0) vn_s[arow] = p;
        }
        __syncthreads();

        // ---- A fragments to registers once (16 regs, 4 ldsm) ----
        uint32_t af[4][4];
        #pragma unroll
        for (int kk = 0; kk < 4; kk++)
            ldsm4(af[kk][0], af[kk][1], af[kk][2], af[kk][3], ah_base + kk * 32);

        // ---- 8 subchunks of 32 cols: MMA + immediate scoring ----
        R3 runL = {INFF, INFF, 0}, runH = runL;

        #pragma unroll 1
        for (int sc = 0; sc < 8; sc++) {
            const int cbase = ch * 256 + sc * 32;
            const uint32_t bsc = bh_base + (uint32_t)cbase * 144;
            float acc[4][4];
            #pragma unroll
            for (int nb = 0; nb < 4; nb++)
                #pragma unroll
                for (int q = 0; q < 4; q++) acc[nb][q] = 0.f;

            #pragma unroll
            for (int kk = 0; kk < 4; kk++) {
                uint32_t h0, h1, h2, h3;
                ldsm4(h0, h1, h2, h3, bsc + kk * 32);
                mma16816(acc[0], af[kk], h0, h1);
                mma16816(acc[1], af[kk], h2, h3);
                uint32_t g0, g1, g2, g3;
                ldsm4(g0, g1, g2, g3, bsc + 16 * 144 + kk * 32);
                mma16816(acc[2], af[kk], g0, g1);
                mma16816(acc[3], af[kk], g2, g3);
            }

            float lbL = INFF, lsL = INFF, lbH = INFF, lsH = INFF;
            int liL = 0, liH = 0;
            #pragma unroll
            for (int nb = 0; nb < 4; nb++) {
                int c0 = cbase + nb * 8 + col2;
                float2 cn2 = *(const float2*)&cnsm[c0];
                SCORE(acc[nb][0] + cn2.x, c0,     lbL, lsL, liL);
                SCORE(acc[nb][1] + cn2.y, c0 + 1, lbL, lsL, liL);
                SCORE(acc[nb][2] + cn2.x, c0,     lbH, lsH, liH);
                SCORE(acc[nb][3] + cn2.y, c0 + 1, lbH, lsH, liH);
            }
            R3 cl = {lbL, lsL, liL}, chh = {lbH, lsH, liH};
            mergeR(runL, cl);
            mergeR(runH, chh);
        }

        // ---- quad reduce (lanes covering same rows) ----
        #pragma unroll
        for (int m = 1; m <= 2; m <<= 1) {
            R3 o;
            o.b = __shfl_xor_sync(0xffffffffu, runL.b, m);
            o.s = __shfl_xor_sync(0xffffffffu, runL.s, m);
            o.i = __shfl_xor_sync(0xffffffffu, runL.i, m);
            mergeR(runL, o);
            o.b = __shfl_xor_sync(0xffffffffu, runH.b, m);
            o.s = __shfl_xor_sync(0xffffffffu, runH.s, m);
            o.i = __shfl_xor_sync(0xffffffffu, runH.i, m);
            mergeR(runH, o);
        }
        if ((lane & 3) == 0) {
            int rL = mb * 16 + (lane >> 2), rH = rL + 8;
            keyf[ch * 64 + rL] = runL.b; keyi[ch * 64 + rL] = runL.i; secf[ch * 64 + rL] = runL.s;
            keyf[ch * 64 + rH] = runH.b; keyi[ch * 64 + rH] = runH.i; secf[ch * 64 + rH] = runH.s;
        }
        __syncthreads();

        // ---- cross-half merge, z, flag, loss ----
        const long i0 = (long)tile * TILE_M;
        if (tid < TILE_M) {
            float b0 = keyf[tid], b1 = keyf[64 + tid];
            float s01 = fminf(fminf(secf[tid], secf[64 + tid]), fmaxf(b0, b1));
            int   zi = (b1 < b0) ? keyi[64 + tid] : keyi[tid];
            float bb = fminf(b0, b1);
            zrow[tid] = zi;
            out_z[i0 + tid] = (float)zi;
            redrow[tid] = fmaxf(vn_s[tid] + bb, 0.0f);
            if (s01 - bb <= TAU) {
                int p = atomicAdd_block(fcnt, 1);
                if (p < FLGMAX) flg[p] = (int)(i0 + tid);
            }
        }
        __syncthreads();

        // ---- gather vecs_hat = codebook[z]; per-tile loss sum ----
        for (int n = tid; n < TILE_M * (KDIM / 4); n += NT) {
            int row = n >> 4, q = n & 15;
            float4 v = __ldg((const float4*)(cb + (long)zrow[row] * KDIM) + q);
            *(float4*)(out + (i0 + row) * KDIM + q * 4) = v;
        }
        if (wid == 0) {
            float s = redrow[lane] + redrow[lane + 32];
            #pragma unroll
            for (int o = 16; o > 0; o >>= 1) s += __shfl_down_sync(0xffffffffu, s, o);
            if (lane == 0) g_tilesum[tile] = s;
        }
        __syncthreads();   // AH / vn_s free to overwrite next iteration
    }

    // ---- inline exact cleanup (bit-identical reference rounding) ----
    {
        const int cnt = fcnt[0] < FLGMAX ? fcnt[0] : FLGMAX;
        for (int f = wid; f < cnt; f += NT / 32) {
            const int i = flg[f];
            const float* v = vecs + (long)i * KDIM;
            float vn = 0.f;
            #pragma unroll
            for (int q = 0; q < KDIM / 4; q++) {
                float4 t = __ldg((const float4*)v + q);
                vn = fmaf(t.x, t.x, vn);
                vn = fmaf(t.y, t.y, vn);
                vn = fmaf(t.z, t.z, vn);
                vn = fmaf(t.w, t.w, vn);
            }
            ull bk = ~0ull;
            for (int jj = 0; jj < 16; jj++) {
                int s = lane * 16 + jj;
                const float* c = cb + (long)s * KDIM;
                float ae = 0.f, ao = 0.f;
                #pragma unroll
                for (int kp = 0; kp < KDIM / 2; kp++) {
                    ae = fmaf(v[2 * kp],     c[2 * kp],     ae);
                    ao = fmaf(v[2 * kp + 1], c[2 * kp + 1], ao);
                }
                float dot = __fadd_rn(ae, ao);
                float d = __fadd_rn(__fmaf_rn(-2.0f, dot, vn), cnsm[s]);
                ull key = ((ull)__float_as_uint(d) << 32) | (unsigned)s;
                bk = key < bk ? key : bk;
            }
            #pragma unroll
            for (int o = 16; o > 0; o >>= 1) {
                ull other = __shfl_xor_sync(0xffffffffu, bk, o);
                bk = other < bk ? other : bk;
            }
            int z = (int)(bk & 0xffffffffull);
            if (lane == 0) out_z[i] = (float)z;
            out[(long)i * KDIM + lane]      = __ldg(&cb[(long)z * KDIM + lane]);
            out[(long)i * KDIM + lane + 32] = __ldg(&cb[(long)z * KDIM + lane + 32]);
        }
    }

    // ---- last CTA: fixed-order loss reduction ----
    __syncthreads();
    if (tid < 32) {
        unsigned t = 0xffffffffu;
        if (tid == 0) { __threadfence(); t = atomicAdd(&g_ticket, 1u); }
        t = __shfl_sync(0xffffffffu, t, 0);
        if (t == (unsigned)(nctas - 1)) {
            __threadfence();
            double s = 0.0;
            for (int j = 0; j < NTILES / 32; j++)
                s += (double)__ldcg(&g_tilesum[lane * (NTILES / 32) + j]);
            #pragma unroll
            for (int o = 16; o > 0; o >>= 1) s += __shfl_down_sync(0xffffffffu, s, o);
            if (lane == 0) {
                float mean = (float)(s / (double)N);
                long base = (long)N * KDIM + N;
                out[base]     = mean;   // l_commit
                out[base + 1] = mean;   // l_codebook (identical forward value)
                g_ticket = 0;
            }
        }
    }
}

extern "C" void kernel_launch(void* const* d_in, const int* in_sizes, int n_in,
                              void* d_out, int out_size) {
    const float* vecs = (const float*)d_in[0];
    const float* cb   = (const float*)d_in[1];
    float* out = (float*)d_out;

    int N = in_sizes[0] / KDIM;          // 65536
    int ntiles = N / TILE_M;             // 1024

    cudaFuncSetAttribute(vq_all, cudaFuncAttributeMaxDynamicSharedMemorySize, SMEM_TOTAL);
    vq_all<<<NCTAS, NT, SMEM_TOTAL>>>(vecs, cb, out, N, ntiles, NCTAS);
}

// round 12
// speedup vs baseline: 1.6613x; 1.6613x over previous
#include <cuda_runtime.h>
#include <cstdint>

#define KDIM 64
#define SDIM 512
#define TILE 64
#define NT 512
#define NWARP 16
#define GRID 148
#define NTILES 1024

typedef unsigned long long ull;

__device__ float    g_tilesum[NTILES];
__device__ unsigned g_ticket;

__device__ __forceinline__ void ffma2(ull& d, ull a, ull b) {
    asm volatile("fma.rn.f32x2 %0, %1, %2, %0;" : "+l"(d) : "l"(a), "l"(b));
}
__device__ __forceinline__ void cp16(void* dst, const void* src) {
    unsigned d;
    asm("{ .reg .u64 t; cvta.to.shared.u64 t, %1; cvt.u32.u64 %0, t; }" : "=r"(d) : "l"(dst));
    asm volatile("cp.async.cg.shared.global [%0], [%1], 16;" :: "r"(d), "l"(src));
}
__device__ __forceinline__ void cp_commit() { asm volatile("cp.async.commit_group;"); }

// monotone float<->uint encoding (total order matching float <)
__device__ __forceinline__ unsigned fenc(float f) {
    unsigned b = __float_as_uint(f);
    return b ^ ((unsigned)((int)b >> 31) | 0x80000000u);
}
__device__ __forceinline__ float fdec(unsigned e) {
    unsigned b = e ^ ((unsigned)((int)(~e) >> 31) | 0x80000000u);
    return __uint_as_float(b);
}

// ---------------------------------------------------------------------------
// Persistent exact-FFMA kernel. Lane owns one codeword (registers); vector
// tile broadcast from smem. Exact reference rounding -> no cleanup needed.
// ---------------------------------------------------------------------------
__global__ void __launch_bounds__(NT, 1)
vq_ffma(const float* __restrict__ vecs, const float* __restrict__ cb,
        float* __restrict__ out, int N, int ntiles, int nctas)
{
    __shared__ float stg[2][TILE * KDIM];   // 32 KB double-buffered A tiles
    __shared__ float vn_s[TILE];
    __shared__ ull   kbuf[TILE * 17];       // padded: (t*17+w) -> 2-way max
    __shared__ int   zrow[TILE];
    __shared__ float redr[TILE];

    const int tid  = threadIdx.x;
    const int lane = tid & 31;
    const int wid  = tid >> 5;
    const int cw   = wid * 32 + lane;       // this lane's codeword

    // ---- stage first A tile ----
    {
        const char* src = (const char*)(vecs + (long)blockIdx.x * TILE * KDIM);
        #pragma unroll
        for (int r = 0; r < 2; r++) {
            int n = r * NT + tid;
            cp16((char*)&stg[0][0] + n * 16, src + n * 16);
        }
    }
    cp_commit();

    // ---- codeword -> registers (pairs for f32x2), and exact norm ----
    ull bfrag[32];
    float cn;
    {
        const float4* bp = (const float4*)(cb + (long)cw * KDIM);
        float a = 0.f;
        #pragma unroll
        for (int q = 0; q < 16; q++) {
            float4 v = __ldg(bp + q);
            a = fmaf(v.x, v.x, a);
            a = fmaf(v.y, v.y, a);
            a = fmaf(v.z, v.z, a);
            a = fmaf(v.w, v.w, a);
            float2 p0 = make_float2(v.x, v.y);
            float2 p1 = make_float2(v.z, v.w);
            bfrag[2 * q]     = *(ull*)&p0;
            bfrag[2 * q + 1] = *(ull*)&p1;
        }
        cn = a;
    }

    float* out_z = out + (long)N * KDIM;
    int buf = 0;

    for (int tile = blockIdx.x; tile < ntiles; tile += nctas) {
        asm volatile("cp.async.wait_group 0;");
        __syncthreads();   // stage[buf] ready

        // ---- per-vector norms (exact float4 chain) ----
        if (tid < TILE) {
            const float4* r = (const float4*)&stg[buf][tid * KDIM];
            float a = 0.f;
            #pragma unroll
            for (int q = 0; q < 16; q++) {
                float4 v = r[q];
                a = fmaf(v.x, v.x, a);
                a = fmaf(v.y, v.y, a);
                a = fmaf(v.z, v.z, a);
                a = fmaf(v.w, v.w, a);
            }
            vn_s[tid] = a;
        }
        // ---- prefetch next tile into the other buffer ----
        if (tile + nctas < ntiles) {
            const char* src = (const char*)(vecs + (long)(tile + nctas) * TILE * KDIM);
            #pragma unroll
            for (int r = 0; r < 2; r++) {
                int n = r * NT + tid;
                cp16((char*)&stg[buf ^ 1][0] + n * 16, src + n * 16);
            }
        }
        cp_commit();
        __syncthreads();   // vn_s visible

        // ---- mainloop: 16 steps of 4 vectors, broadcast A, register B ----
        const float* st = &stg[buf][0];
        #pragma unroll 1
        for (int v0 = 0; v0 < TILE; v0 += 4) {
            ull acc0 = 0ull, acc1 = 0ull, acc2 = 0ull, acc3 = 0ull;
            const float* p0 = st + (v0 + 0) * KDIM;
            const float* p1 = st + (v0 + 1) * KDIM;
            const float* p2 = st + (v0 + 2) * KDIM;
            const float* p3 = st + (v0 + 3) * KDIM;
            #pragma unroll 2
            for (int kq = 0; kq < 16; kq++) {
                ulonglong2 a0 = *(const ulonglong2*)(p0 + kq * 4);
                ulonglong2 a1 = *(const ulonglong2*)(p1 + kq * 4);
                ulonglong2 a2 = *(const ulonglong2*)(p2 + kq * 4);
                ulonglong2 a3 = *(const ulonglong2*)(p3 + kq * 4);
                ffma2(acc0, a0.x, bfrag[2 * kq]); ffma2(acc0, a0.y, bfrag[2 * kq + 1]);
                ffma2(acc1, a1.x, bfrag[2 * kq]); ffma2(acc1, a1.y, bfrag[2 * kq + 1]);
                ffma2(acc2, a2.x, bfrag[2 * kq]); ffma2(acc2, a2.y, bfrag[2 * kq + 1]);
                ffma2(acc3, a3.x, bfrag[2 * kq]); ffma2(acc3, a3.y, bfrag[2 * kq + 1]);
            }
            ull accs[4] = {acc0, acc1, acc2, acc3};
            #pragma unroll
            for (int j = 0; j < 4; j++) {
                float lo = __uint_as_float((unsigned)(accs[j] & 0xffffffffull));
                float hi = __uint_as_float((unsigned)(accs[j] >> 32));
                float dot = __fadd_rn(lo, hi);
                // exact reference rounding: d = fl(fl(vn - 2*dot) + cn)
                float d = __fadd_rn(__fmaf_rn(-2.0f, dot, vn_s[v0 + j]), cn);
                unsigned e = fenc(d);
                unsigned m = __reduce_min_sync(0xffffffffu, e);
                unsigned bal = __ballot_sync(0xffffffffu, e == m);
                int lmin = __ffs(bal) - 1;    // lowest lane = lowest s in warp
                if (lane == lmin)
                    kbuf[(v0 + j) * 17 + wid] =
                        ((ull)m << 32) | (unsigned)(wid * 32 + lmin);
            }
        }
        __syncthreads();   // kbuf complete

        // ---- cross-warp merge (lexicographic: score then lowest s) ----
        const long i0 = (long)tile * TILE;
        if (tid < TILE) {
            ull bk = kbuf[tid * 17];
            #pragma unroll
            for (int w = 1; w < NWARP; w++) {
                ull k = kbuf[tid * 17 + w];
                bk = k < bk ? k : bk;
            }
            float d = fdec((unsigned)(bk >> 32));
            int z = (int)(bk & 0xffffffffull);
            zrow[tid] = z;
            out_z[i0 + tid] = (float)z;
            redr[tid] = fmaxf(d, 0.0f);
        }
        __syncthreads();   // zrow/redr visible

        // ---- gather vecs_hat = codebook[z]; per-tile loss sum ----
        #pragma unroll
        for (int r = 0; r < 2; r++) {
            int n = r * NT + tid;
            int row = n >> 4, q = n & 15;
            float4 v = __ldg((const float4*)(cb + (long)zrow[row] * KDIM) + q);
            *(float4*)(out + (i0 + row) * KDIM + q * 4) = v;
        }
        if (wid == 0) {
            float s = redr[lane] + redr[lane + 32];
            #pragma unroll
            for (int o = 16; o > 0; o >>= 1) s += __shfl_down_sync(0xffffffffu, s, o);
            if (lane == 0) g_tilesum[tile] = s;
        }
        buf ^= 1;
        __syncthreads();
    }

    // ---- last CTA: fixed-order loss reduction ----
    if (tid < 32) {
        unsigned t = 0xffffffffu;
        if (tid == 0) { __threadfence(); t = atomicAdd(&g_ticket, 1u); }
        t = __shfl_sync(0xffffffffu, t, 0);
        if (t == (unsigned)(nctas - 1)) {
            __threadfence();
            double s = 0.0;
            for (int j = 0; j < NTILES / 32; j++)
                s += (double)__ldcg(&g_tilesum[lane * (NTILES / 32) + j]);
            #pragma unroll
            for (int o = 16; o > 0; o >>= 1) s += __shfl_down_sync(0xffffffffu, s, o);
            if (lane == 0) {
                float mean = (float)(s / (double)N);
                long base = (long)N * KDIM + N;
                out[base]     = mean;   // l_commit
                out[base + 1] = mean;   // l_codebook (identical forward value)
                g_ticket = 0;
            }
        }
    }
}

extern "C" void kernel_launch(void* const* d_in, const int* in_sizes, int n_in,
                              void* d_out, int out_size) {
    const float* vecs = (const float*)d_in[0];
    const float* cb   = (const float*)d_in[1];
    float* out = (float*)d_out;

    int N = in_sizes[0] / KDIM;          // 65536
    int ntiles = N / TILE;               // 1024

    vq_ffma<<<GRID, NT>>>(vecs, cb, out, N, ntiles, GRID);
}

// round 13
// speedup vs baseline: 3.0067x; 1.8099x over previous
#include <cuda_runtime.h>
#include <cstdint>

#define KDIM 64
#define SDIM 512
#define TILE 32             // vectors per CTA tile
#define NT 256
#define NWARP 8
#define GRID 148
#define NTILES 2048         // 65536 / 32
#define PITCH 68            // floats/row: float4 lane-stride 17 (mod 8) conflict-free

// smem byte offsets
#define OFF_CB   0          // 512 * 68 * 4 = 139264 (codebook, pitched)
#define OFF_STG  139264     // 2 * 32 * 68 * 4 = 17408 (A tiles, pitched, dbl-buf)
#define OFF_CN   156672     // 512 * 4
#define OFF_VN   158720     // 32 * 4
#define OFF_KB   158848     // 32 * 8 * 8 (u64 keys [v][warp])
#define OFF_ZR   160896     // 32 * 4
#define OFF_RED  161024     // 32 * 4
#define SMEM_TOTAL 161152

typedef unsigned long long ull;

__device__ float    g_tilesum[NTILES];
__device__ unsigned g_ticket;

__device__ __forceinline__ void ffma2(ull& d, ull a, ull b) {
    asm volatile("fma.rn.f32x2 %0, %1, %2, %0;" : "+l"(d) : "l"(a), "l"(b));
}
__device__ __forceinline__ void cp16(void* dst, const void* src) {
    unsigned d;
    asm("{ .reg .u64 t; cvta.to.shared.u64 t, %1; cvt.u32.u64 %0, t; }" : "=r"(d) : "l"(dst));
    asm volatile("cp.async.cg.shared.global [%0], [%1], 16;" :: "r"(d), "l"(src));
}
__device__ __forceinline__ void cp_commit() { asm volatile("cp.async.commit_group;"); }

// monotone float<->uint encoding (total order matching float <), validated R12
__device__ __forceinline__ unsigned fenc(float f) {
    unsigned b = __float_as_uint(f);
    return b ^ ((unsigned)((int)b >> 31) | 0x80000000u);
}
__device__ __forceinline__ float fdec(unsigned e) {
    unsigned b = e ^ ((unsigned)((int)(~e) >> 31) | 0x80000000u);
    return __uint_as_float(b);
}

// ---------------------------------------------------------------------------
// Persistent exact-FFMA kernel, 8x8 lane tiles (phase/fma balanced), 1 CTA/SM.
// Lane (lv,lc): vectors v = 4*ii+lv (ii<8), codewords c = wid*64 + lc + 8*jj.
// Exact reference rounding everywhere -> no cleanup pass needed.
// ---------------------------------------------------------------------------
__global__ void __launch_bounds__(NT, 1)
vq_main(const float* __restrict__ vecs, const float* __restrict__ cb,
        float* __restrict__ out, int N, int ntiles, int nctas)
{
    extern __shared__ char smb[];
    float* cbs  = (float*)(smb + OFF_CB);
    float* stg  = (float*)(smb + OFF_STG);
    float* cns  = (float*)(smb + OFF_CN);
    float* vns  = (float*)(smb + OFF_VN);
    ull*   kbuf = (ull*)(smb + OFF_KB);
    int*   zr   = (int*)(smb + OFF_ZR);
    float* rd   = (float*)(smb + OFF_RED);

    const int tid  = threadIdx.x;
    const int lane = tid & 31;
    const int wid  = tid >> 5;
    const int lv   = lane >> 3;       // vector sub-row 0..3
    const int lc   = lane & 7;        // codeword sub-col 0..7
    const int wbase = wid * 64;

    // ---- prologue: codebook -> pitched smem, first A tile, cnorm ----
    for (int n = tid; n < SDIM * 16; n += NT) {
        int row = n >> 4, q = n & 15;
        cp16(cbs + row * PITCH + q * 4, cb + row * KDIM + q * 4);
    }
    {
        const float* src = vecs + (long)blockIdx.x * TILE * KDIM;
        for (int n = tid; n < TILE * 16; n += NT) {
            int row = n >> 4, q = n & 15;
            cp16(stg + row * PITCH + q * 4, src + row * KDIM + q * 4);
        }
    }
    cp_commit();

    #pragma unroll
    for (int r = 0; r < SDIM / NT; r++) {
        int s = r * NT + tid;
        const float4* row = (const float4*)(cb + (long)s * KDIM);
        float a = 0.f;
        #pragma unroll
        for (int q = 0; q < 16; q++) {
            float4 v = __ldg(row + q);
            a = fmaf(v.x, v.x, a);
            a = fmaf(v.y, v.y, a);
            a = fmaf(v.z, v.z, a);
            a = fmaf(v.w, v.w, a);
        }
        cns[s] = a;
    }
    __syncthreads();

    // lane's codeword norms -> registers (8 floats)
    float cnr[8];
    #pragma unroll
    for (int jj = 0; jj < 8; jj++) cnr[jj] = cns[wbase + lc + 8 * jj];

    const float* bb = cbs + (wbase + lc) * PITCH;   // lane's B base (8 rows, +8*PITCH)
    float* out_z = out + (long)N * KDIM;
    int buf = 0;

    for (int tile = blockIdx.x; tile < ntiles; tile += nctas) {
        asm volatile("cp.async.wait_group 0;");
        __syncthreads();   // stg[buf] ready; prior tile fully consumed

        const float* st = stg + buf * (TILE * PITCH);

        // per-vector norms (exact float4 chain), warp 0
        if (tid < TILE) {
            const float* vr = st + tid * PITCH;
            float a = 0.f;
            #pragma unroll
            for (int q = 0; q < 16; q++) {
                float4 v = *(const float4*)(vr + q * 4);
                a = fmaf(v.x, v.x, a);
                a = fmaf(v.y, v.y, a);
                a = fmaf(v.z, v.z, a);
                a = fmaf(v.w, v.w, a);
            }
            vns[tid] = a;
        }
        // prefetch next A tile
        if (tile + nctas < ntiles) {
            const float* src = vecs + (long)(tile + nctas) * TILE * KDIM;
            float* dst = stg + (buf ^ 1) * (TILE * PITCH);
            for (int n = tid; n < TILE * 16; n += NT) {
                int row = n >> 4, q = n & 15;
                cp16(dst + row * PITCH + q * 4, src + row * KDIM + q * 4);
            }
        }
        cp_commit();
        __syncthreads();   // vns visible

        // ---- mainloop: 16 ksteps, 8x8 ull accumulators ----
        ull acc[8][8];
        #pragma unroll
        for (int ii = 0; ii < 8; ii++)
            #pragma unroll
            for (int jj = 0; jj < 8; jj++) acc[ii][jj] = 0ull;

        const float* ab = st + lv * PITCH;

        #pragma unroll 1
        for (int kc = 0; kc < 16; kc++) {
            ulonglong2 af[8], bf[8];
            #pragma unroll
            for (int ii = 0; ii < 8; ii++)
                af[ii] = *(const ulonglong2*)(ab + ii * 4 * PITCH + kc * 4);
            #pragma unroll
            for (int jj = 0; jj < 8; jj++)
                bf[jj] = *(const ulonglong2*)(bb + jj * 8 * PITCH + kc * 4);
            #pragma unroll
            for (int ii = 0; ii < 8; ii++)
                #pragma unroll
                for (int jj = 0; jj < 8; jj++) {
                    ffma2(acc[ii][jj], af[ii].x, bf[jj].x);
                    ffma2(acc[ii][jj], af[ii].y, bf[jj].y);
                }
        }

        // ---- epilogue: exact scores, per-vector argmin (lowest-s ties) ----
        #pragma unroll
        for (int ii = 0; ii < 8; ii++) {
            const int v = 4 * ii + lv;
            const float vn = vns[v];
            ull bk = ~0ull;
            #pragma unroll
            for (int jj = 0; jj < 8; jj++) {
                float lo = __uint_as_float((unsigned)(acc[ii][jj] & 0xffffffffull));
                float hi = __uint_as_float((unsigned)(acc[ii][jj] >> 32));
                float dot = __fadd_rn(lo, hi);
                float d = __fadd_rn(__fmaf_rn(-2.0f, dot, vn), cnr[jj]);
                ull key = ((ull)fenc(d) << 32) | (unsigned)(wbase + lc + 8 * jj);
                bk = key < bk ? key : bk;
            }
            #pragma unroll
            for (int m = 1; m <= 4; m <<= 1) {
                ull o = __shfl_xor_sync(0xffffffffu, bk, m);
                bk = o < bk ? o : bk;
            }
            if (lc == 0) kbuf[v * 8 + wid] = bk;
        }
        __syncthreads();   // kbuf complete

        // ---- cross-warp merge; z, err ----
        const long i0 = (long)tile * TILE;
        if (tid < TILE) {
            ull bk = kbuf[tid * 8];
            #pragma unroll
            for (int w = 1; w < NWARP; w++) {
                ull k = kbuf[tid * 8 + w];
                bk = k < bk ? k : bk;
            }
            float d = fdec((unsigned)(bk >> 32));
            int z = (int)(bk & 0xffffffffull);
            zr[tid] = z;
            out_z[i0 + tid] = (float)z;
            rd[tid] = fmaxf(d, 0.0f);
        }
        __syncthreads();   // zr/rd visible

        // ---- gather vecs_hat = codebook[z] from smem; per-tile loss sum ----
        #pragma unroll
        for (int r = 0; r < 2; r++) {
            int n = r * NT + tid;
            int row = n >> 4, q = n & 15;
            float4 v = *(const float4*)(cbs + (long)zr[row] * PITCH + q * 4);
            *(float4*)(out + (i0 + row) * KDIM + q * 4) = v;
        }
        if (wid == 0) {
            float s = rd[lane];
            #pragma unroll
            for (int o = 16; o > 0; o >>= 1) s += __shfl_down_sync(0xffffffffu, s, o);
            if (lane == 0) g_tilesum[tile] = s;
        }
        buf ^= 1;
        __syncthreads();
    }

    // ---- last CTA: fixed-order loss reduction ----
    if (tid < 32) {
        unsigned t = 0xffffffffu;
        if (tid == 0) { __threadfence(); t = atomicAdd(&g_ticket, 1u); }
        t = __shfl_sync(0xffffffffu, t, 0);
        if (t == (unsigned)(nctas - 1)) {
            __threadfence();
            double s = 0.0;
            for (int j = 0; j < NTILES / 32; j++)
                s += (double)__ldcg(&g_tilesum[lane * (NTILES / 32) + j]);
            #pragma unroll
            for (int o = 16; o > 0; o >>= 1) s += __shfl_down_sync(0xffffffffu, s, o);
            if (lane == 0) {
                float mean = (float)(s / (double)N);
                long base = (long)N * KDIM + N;
                out[base]     = mean;   // l_commit
                out[base + 1] = mean;   // l_codebook (identical forward value)
                g_ticket = 0;
            }
        }
    }
}

extern "C" void kernel_launch(void* const* d_in, const int* in_sizes, int n_in,
                              void* d_out, int out_size) {
    const float* vecs = (const float*)d_in[0];
    const float* cb   = (const float*)d_in[1];
    float* out = (float*)d_out;

    int N = in_sizes[0] / KDIM;          // 65536
    int ntiles = N / TILE;               // 2048

    cudaFuncSetAttribute(vq_main, cudaFuncAttributeMaxDynamicSharedMemorySize, SMEM_TOTAL);
    vq_main<<<GRID, NT, SMEM_TOTAL>>>(vecs, cb, out, N, ntiles, GRID);
}

// round 14
// speedup vs baseline: 3.0419x; 1.0117x over previous
#include <cuda_runtime.h>
#include <cstdint>

#define KDIM 64
#define SDIM 512
#define TILE 32             // vectors per CTA tile
#define NT 256
#define NWARP 8
#define GRID 148
#define NTILES 2048         // 65536 / 32
#define PITCH 68            // floats/row; padding floats 64..67 absorbs prefetch overshoot

// smem byte offsets
#define OFF_CB   0          // 512 * 68 * 4 = 139264 (codebook, pitched)
#define OFF_STG  139264     // 2 * 32 * 68 * 4 = 17408 (A tiles, pitched, dbl-buf)
#define OFF_CN   156672     // 512 * 4
#define OFF_VN   158720     // 32 * 4
#define OFF_KB   158848     // 32 * 8 * 8 (u64 keys [v][warp])
#define OFF_ZR   160896     // 32 * 4
#define OFF_RED  161024     // 32 * 4
#define SMEM_TOTAL 161152

typedef unsigned long long ull;

__device__ float    g_tilesum[NTILES];
__device__ unsigned g_ticket;

__device__ __forceinline__ void ffma2(ull& d, ull a, ull b) {
    asm volatile("fma.rn.f32x2 %0, %1, %2, %0;" : "+l"(d) : "l"(a), "l"(b));
}
__device__ __forceinline__ void cp16(void* dst, const void* src) {
    unsigned d;
    asm("{ .reg .u64 t; cvta.to.shared.u64 t, %1; cvt.u32.u64 %0, t; }" : "=r"(d) : "l"(dst));
    asm volatile("cp.async.cg.shared.global [%0], [%1], 16;" :: "r"(d), "l"(src));
}
__device__ __forceinline__ void cp_commit() { asm volatile("cp.async.commit_group;"); }

// monotone float<->uint encoding (total order matching float <), validated R12/R13
__device__ __forceinline__ unsigned fenc(float f) {
    unsigned b = __float_as_uint(f);
    return b ^ ((unsigned)((int)b >> 31) | 0x80000000u);
}
__device__ __forceinline__ float fdec(unsigned e) {
    unsigned b = e ^ ((unsigned)((int)(~e) >> 31) | 0x80000000u);
    return __uint_as_float(b);
}

// ---------------------------------------------------------------------------
// Persistent exact-FFMA kernel, 8x8 lane tiles, software-pipelined k-steps.
// Lane (lv,lc): vectors v = 4*ii+lv, codewords c = wid*64 + lc + 8*jj.
// Exact reference rounding everywhere -> no cleanup pass needed.
// ---------------------------------------------------------------------------
__global__ void __launch_bounds__(NT, 1)
vq_main(const float* __restrict__ vecs, const float* __restrict__ cb,
        float* __restrict__ out, int N, int ntiles, int nctas)
{
    extern __shared__ char smb[];
    float* cbs  = (float*)(smb + OFF_CB);
    float* stg  = (float*)(smb + OFF_STG);
    float* cns  = (float*)(smb + OFF_CN);
    float* vns  = (float*)(smb + OFF_VN);
    ull*   kbuf = (ull*)(smb + OFF_KB);
    int*   zr   = (int*)(smb + OFF_ZR);
    float* rd   = (float*)(smb + OFF_RED);

    const int tid  = threadIdx.x;
    const int lane = tid & 31;
    const int wid  = tid >> 5;
    const int lv   = lane >> 3;       // vector sub-row 0..3
    const int lc   = lane & 7;        // codeword sub-col 0..7
    const int wbase = wid * 64;

    // ---- prologue: codebook -> pitched smem, first A tile, cnorm ----
    for (int n = tid; n < SDIM * 16; n += NT) {
        int row = n >> 4, q = n & 15;
        cp16(cbs + row * PITCH + q * 4, cb + row * KDIM + q * 4);
    }
    {
        const float* src = vecs + (long)blockIdx.x * TILE * KDIM;
        for (int n = tid; n < TILE * 16; n += NT) {
            int row = n >> 4, q = n & 15;
            cp16(stg + row * PITCH + q * 4, src + row * KDIM + q * 4);
        }
    }
    cp_commit();

    #pragma unroll
    for (int r = 0; r < SDIM / NT; r++) {
        int s = r * NT + tid;
        const float4* row = (const float4*)(cb + (long)s * KDIM);
        float a = 0.f;
        #pragma unroll
        for (int q = 0; q < 16; q++) {
            float4 v = __ldg(row + q);
            a = fmaf(v.x, v.x, a);
            a = fmaf(v.y, v.y, a);
            a = fmaf(v.z, v.z, a);
            a = fmaf(v.w, v.w, a);
        }
        cns[s] = a;
    }
    __syncthreads();

    // lane's codeword norms -> registers (8 floats)
    float cnr[8];
    #pragma unroll
    for (int jj = 0; jj < 8; jj++) cnr[jj] = cns[wbase + lc + 8 * jj];

    const float* bb = cbs + (wbase + lc) * PITCH;   // lane's B base (rows +8*PITCH)
    float* out_z = out + (long)N * KDIM;
    int buf = 0;

    for (int tile = blockIdx.x; tile < ntiles; tile += nctas) {
        asm volatile("cp.async.wait_group 0;");
        __syncthreads();   // stg[buf] ready; prior tile fully consumed

        const float* st = stg + buf * (TILE * PITCH);

        // per-vector norms (exact float4 chain), warp 0
        if (tid < TILE) {
            const float* vr = st + tid * PITCH;
            float a = 0.f;
            #pragma unroll
            for (int q = 0; q < 16; q++) {
                float4 v = *(const float4*)(vr + q * 4);
                a = fmaf(v.x, v.x, a);
                a = fmaf(v.y, v.y, a);
                a = fmaf(v.z, v.z, a);
                a = fmaf(v.w, v.w, a);
            }
            vns[tid] = a;
        }
        // prefetch next A tile
        if (tile + nctas < ntiles) {
            const float* src = vecs + (long)(tile + nctas) * TILE * KDIM;
            float* dst = stg + (buf ^ 1) * (TILE * PITCH);
            for (int n = tid; n < TILE * 16; n += NT) {
                int row = n >> 4, q = n & 15;
                cp16(dst + row * PITCH + q * 4, src + row * KDIM + q * 4);
            }
        }
        cp_commit();
        __syncthreads();   // vns visible

        // ---- mainloop: 32 k-steps of 2 floats, double-buffered operands ----
        ull acc[8][8];
        #pragma unroll
        for (int ii = 0; ii < 8; ii++)
            #pragma unroll
            for (int jj = 0; jj < 8; jj++) acc[ii][jj] = 0ull;

        const float* ab = st + lv * PITCH;

        ull afr[2][8], bfr[2][8];
        #pragma unroll
        for (int ii = 0; ii < 8; ii++) afr[0][ii] = *(const ull*)(ab + ii * 4 * PITCH);
        #pragma unroll
        for (int jj = 0; jj < 8; jj++) bfr[0][jj] = *(const ull*)(bb + jj * 8 * PITCH);

        #pragma unroll 1
        for (int ks = 0; ks < 32; ks += 2) {
            // prefetch step ks+1 into buffer 1, compute step ks from buffer 0
            #pragma unroll
            for (int ii = 0; ii < 8; ii++)
                afr[1][ii] = *(const ull*)(ab + ii * 4 * PITCH + (ks + 1) * 2);
            #pragma unroll
            for (int jj = 0; jj < 8; jj++)
                bfr[1][jj] = *(const ull*)(bb + jj * 8 * PITCH + (ks + 1) * 2);
            #pragma unroll
            for (int ii = 0; ii < 8; ii++)
                #pragma unroll
                for (int jj = 0; jj < 8; jj++)
                    ffma2(acc[ii][jj], afr[0][ii], bfr[0][jj]);

            // prefetch step ks+2 into buffer 0 (overshoot lands in row padding),
            // compute step ks+1 from buffer 1
            #pragma unroll
            for (int ii = 0; ii < 8; ii++)
                afr[0][ii] = *(const ull*)(ab + ii * 4 * PITCH + (ks + 2) * 2);
            #pragma unroll
            for (int jj = 0; jj < 8; jj++)
                bfr[0][jj] = *(const ull*)(bb + jj * 8 * PITCH + (ks + 2) * 2);
            #pragma unroll
            for (int ii = 0; ii < 8; ii++)
                #pragma unroll
                for (int jj = 0; jj < 8; jj++)
                    ffma2(acc[ii][jj], afr[1][ii], bfr[1][jj]);
        }

        // ---- epilogue: exact scores, per-vector argmin (lowest-s ties) ----
        #pragma unroll
        for (int ii = 0; ii < 8; ii++) {
            const int v = 4 * ii + lv;
            const float vn = vns[v];
            ull bk = ~0ull;
            #pragma unroll
            for (int jj = 0; jj < 8; jj++) {
                float lo = __uint_as_float((unsigned)(acc[ii][jj] & 0xffffffffull));
                float hi = __uint_as_float((unsigned)(acc[ii][jj] >> 32));
                float dot = __fadd_rn(lo, hi);
                float d = __fadd_rn(__fmaf_rn(-2.0f, dot, vn), cnr[jj]);
                ull key = ((ull)fenc(d) << 32) | (unsigned)(wbase + lc + 8 * jj);
                bk = key < bk ? key : bk;
            }
            #pragma unroll
            for (int m = 1; m <= 4; m <<= 1) {
                ull o = __shfl_xor_sync(0xffffffffu, bk, m);
                bk = o < bk ? o : bk;
            }
            if (lc == 0) kbuf[v * 8 + wid] = bk;
        }
        __syncthreads();   // kbuf complete

        // ---- cross-warp merge; z, err ----
        const long i0 = (long)tile * TILE;
        if (tid < TILE) {
            ull bk = kbuf[tid * 8];
            #pragma unroll
            for (int w = 1; w < NWARP; w++) {
                ull k = kbuf[tid * 8 + w];
                bk = k < bk ? k : bk;
            }
            float d = fdec((unsigned)(bk >> 32));
            int z = (int)(bk & 0xffffffffull);
            zr[tid] = z;
            out_z[i0 + tid] = (float)z;
            rd[tid] = fmaxf(d, 0.0f);
        }
        __syncthreads();   // zr/rd visible

        // ---- gather vecs_hat = codebook[z] from smem; per-tile loss sum ----
        #pragma unroll
        for (int r = 0; r < 2; r++) {
            int n = r * NT + tid;
            int row = n >> 4, q = n & 15;
            float4 v = *(const float4*)(cbs + (long)zr[row] * PITCH + q * 4);
            *(float4*)(out + (i0 + row) * KDIM + q * 4) = v;
        }
        if (wid == 0) {
            float s = rd[lane];
            #pragma unroll
            for (int o = 16; o > 0; o >>= 1) s += __shfl_down_sync(0xffffffffu, s, o);
            if (lane == 0) g_tilesum[tile] = s;
        }
        buf ^= 1;
        __syncthreads();
    }

    // ---- last CTA: fixed-order loss reduction ----
    if (tid < 32) {
        unsigned t = 0xffffffffu;
        if (tid == 0) { __threadfence(); t = atomicAdd(&g_ticket, 1u); }
        t = __shfl_sync(0xffffffffu, t, 0);
        if (t == (unsigned)(nctas - 1)) {
            __threadfence();
            double s = 0.0;
            for (int j = 0; j < NTILES / 32; j++)
                s += (double)__ldcg(&g_tilesum[lane * (NTILES / 32) + j]);
            #pragma unroll
            for (int o = 16; o > 0; o >>= 1) s += __shfl_down_sync(0xffffffffu, s, o);
            if (lane == 0) {
                float mean = (float)(s / (double)N);
                long base = (long)N * KDIM + N;
                out[base]     = mean;   // l_commit
                out[base + 1] = mean;   // l_codebook (identical forward value)
                g_ticket = 0;
            }
        }
    }
}

extern "C" void kernel_launch(void* const* d_in, const int* in_sizes, int n_in,
                              void* d_out, int out_size) {
    const float* vecs = (const float*)d_in[0];
    const float* cb   = (const float*)d_in[1];
    float* out = (float*)d_out;

    int N = in_sizes[0] / KDIM;          // 65536
    int ntiles = N / TILE;               // 2048

    cudaFuncSetAttribute(vq_main, cudaFuncAttributeMaxDynamicSharedMemorySize, SMEM_TOTAL);
    vq_main<<<GRID, NT, SMEM_TOTAL>>>(vecs, cb, out, N, ntiles, GRID);
}

// round 15
// speedup vs baseline: 3.0493x; 1.0024x over previous
#include <cuda_runtime.h>
#include <cstdint>

#define KDIM 64
#define SDIM 512
#define TILE 32             // vectors per CTA tile
#define NT 256
#define NWARP 8
#define GRID 148
#define NTILES 2048         // 65536 / 32
#define PITCH 68            // floats/row; padding floats 64..67 absorbs prefetch overshoot

// smem byte offsets
#define OFF_CB   0          // 512 * 68 * 4 = 139264 (codebook, pitched)
#define OFF_STG  139264     // 2 * 32 * 68 * 4 = 17408 (A tiles, pitched, dbl-buf)
#define OFF_CN   156672     // 512 * 4
#define OFF_VN   158720     // 32 * 4
#define OFF_KB   158848     // 32 * 8 * 8 (u64 keys [v][warp])
#define OFF_ZR   160896     // 32 * 4
#define OFF_RED  161024     // 32 * 4
#define SMEM_TOTAL 161152

typedef unsigned long long ull;

__device__ float    g_tilesum[NTILES];
__device__ unsigned g_ticket;

__device__ __forceinline__ void ffma2(ull& d, ull a, ull b) {
    asm volatile("fma.rn.f32x2 %0, %1, %2, %0;" : "+l"(d) : "l"(a), "l"(b));
}
__device__ __forceinline__ void cp16(void* dst, const void* src) {
    unsigned d;
    asm("{ .reg .u64 t; cvta.to.shared.u64 t, %1; cvt.u32.u64 %0, t; }" : "=r"(d) : "l"(dst));
    asm volatile("cp.async.cg.shared.global [%0], [%1], 16;" :: "r"(d), "l"(src));
}
__device__ __forceinline__ void cp_commit() { asm volatile("cp.async.commit_group;"); }

// monotone float<->uint encoding (total order matching float <), validated R12-R14
__device__ __forceinline__ unsigned fenc(float f) {
    unsigned b = __float_as_uint(f);
    return b ^ ((unsigned)((int)b >> 31) | 0x80000000u);
}
__device__ __forceinline__ float fdec(unsigned e) {
    unsigned b = e ^ ((unsigned)((int)(~e) >> 31) | 0x80000000u);
    return __uint_as_float(b);
}

// ---------------------------------------------------------------------------
// Persistent exact-FFMA kernel, 8x8 lane tiles. Loads for step k+1 are
// INTERLEAVED into step k's FMA block (4 loads + 16 FMAs x 4 groups) so the
// smem crossbar and the fma pipe run concurrently instead of in bursts.
// Exact reference rounding everywhere -> no cleanup pass needed.
// ---------------------------------------------------------------------------
__global__ void __launch_bounds__(NT, 1)
vq_main(const float* __restrict__ vecs, const float* __restrict__ cb,
        float* __restrict__ out, int N, int ntiles, int nctas)
{
    extern __shared__ char smb[];
    float* cbs  = (float*)(smb + OFF_CB);
    float* stg  = (float*)(smb + OFF_STG);
    float* cns  = (float*)(smb + OFF_CN);
    float* vns  = (float*)(smb + OFF_VN);
    ull*   kbuf = (ull*)(smb + OFF_KB);
    int*   zr   = (int*)(smb + OFF_ZR);
    float* rd   = (float*)(smb + OFF_RED);

    const int tid  = threadIdx.x;
    const int lane = tid & 31;
    const int wid  = tid >> 5;
    const int lv   = lane >> 3;       // vector sub-row 0..3
    const int lc   = lane & 7;        // codeword sub-col 0..7
    const int wbase = wid * 64;

    // ---- prologue: codebook -> pitched smem, first A tile, cnorm ----
    for (int n = tid; n < SDIM * 16; n += NT) {
        int row = n >> 4, q = n & 15;
        cp16(cbs + row * PITCH + q * 4, cb + row * KDIM + q * 4);
    }
    {
        const float* src = vecs + (long)blockIdx.x * TILE * KDIM;
        for (int n = tid; n < TILE * 16; n += NT) {
            int row = n >> 4, q = n & 15;
            cp16(stg + row * PITCH + q * 4, src + row * KDIM + q * 4);
        }
    }
    cp_commit();

    #pragma unroll
    for (int r = 0; r < SDIM / NT; r++) {
        int s = r * NT + tid;
        const float4* row = (const float4*)(cb + (long)s * KDIM);
        float a = 0.f;
        #pragma unroll
        for (int q = 0; q < 16; q++) {
            float4 v = __ldg(row + q);
            a = fmaf(v.x, v.x, a);
            a = fmaf(v.y, v.y, a);
            a = fmaf(v.z, v.z, a);
            a = fmaf(v.w, v.w, a);
        }
        cns[s] = a;
    }
    __syncthreads();

    // lane's codeword norms -> registers (8 floats)
    float cnr[8];
    #pragma unroll
    for (int jj = 0; jj < 8; jj++) cnr[jj] = cns[wbase + lc + 8 * jj];

    const float* bb = cbs + (wbase + lc) * PITCH;   // lane's B base (rows +8*PITCH)
    float* out_z = out + (long)N * KDIM;
    int buf = 0;

    for (int tile = blockIdx.x; tile < ntiles; tile += nctas) {
        asm volatile("cp.async.wait_group 0;");
        __syncthreads();   // stg[buf] ready; prior tile fully consumed

        const float* st = stg + buf * (TILE * PITCH);

        // per-vector norms (exact float4 chain), warp 0
        if (tid < TILE) {
            const float* vr = st + tid * PITCH;
            float a = 0.f;
            #pragma unroll
            for (int q = 0; q < 16; q++) {
                float4 v = *(const float4*)(vr + q * 4);
                a = fmaf(v.x, v.x, a);
                a = fmaf(v.y, v.y, a);
                a = fmaf(v.z, v.z, a);
                a = fmaf(v.w, v.w, a);
            }
            vns[tid] = a;
        }
        // prefetch next A tile
        if (tile + nctas < ntiles) {
            const float* src = vecs + (long)(tile + nctas) * TILE * KDIM;
            float* dst = stg + (buf ^ 1) * (TILE * PITCH);
            for (int n = tid; n < TILE * 16; n += NT) {
                int row = n >> 4, q = n & 15;
                cp16(dst + row * PITCH + q * 4, src + row * KDIM + q * 4);
            }
        }
        cp_commit();
        __syncthreads();   // vns visible

        // ---- mainloop: 32 k-steps; loads interleaved inside FMA blocks ----
        ull acc[8][8];
        #pragma unroll
        for (int ii = 0; ii < 8; ii++)
            #pragma unroll
            for (int jj = 0; jj < 8; jj++) acc[ii][jj] = 0ull;

        const float* ab = st + lv * PITCH;

        ull afr[2][8], bfr[2][8];
        #pragma unroll
        for (int ii = 0; ii < 8; ii++) afr[0][ii] = *(const ull*)(ab + ii * 4 * PITCH);
        #pragma unroll
        for (int jj = 0; jj < 8; jj++) bfr[0][jj] = *(const ull*)(bb + jj * 8 * PITCH);

        #pragma unroll 1
        for (int ks = 0; ks < 32; ks += 2) {
            // -- compute step ks (buf 0); prefetch step ks+1 (buf 1), 4 groups --
            #pragma unroll
            for (int g = 0; g < 4; g++) {
                if (g < 2) {
                    #pragma unroll
                    for (int t = 0; t < 4; t++)
                        afr[1][g * 4 + t] =
                            *(const ull*)(ab + (g * 4 + t) * 4 * PITCH + (ks + 1) * 2);
                } else {
                    #pragma unroll
                    for (int t = 0; t < 4; t++)
                        bfr[1][(g - 2) * 4 + t] =
                            *(const ull*)(bb + ((g - 2) * 4 + t) * 8 * PITCH + (ks + 1) * 2);
                }
                #pragma unroll
                for (int ii = g * 2; ii < g * 2 + 2; ii++)
                    #pragma unroll
                    for (int jj = 0; jj < 8; jj++)
                        ffma2(acc[ii][jj], afr[0][ii], bfr[0][jj]);
            }
            // -- compute step ks+1 (buf 1); prefetch step ks+2 (buf 0) --
            // (ks=30 overshoot reads row floats 64..65, inside PITCH padding)
            #pragma unroll
            for (int g = 0; g < 4; g++) {
                if (g < 2) {
                    #pragma unroll
                    for (int t = 0; t < 4; t++)
                        afr[0][g * 4 + t] =
                            *(const ull*)(ab + (g * 4 + t) * 4 * PITCH + (ks + 2) * 2);
                } else {
                    #pragma unroll
                    for (int t = 0; t < 4; t++)
                        bfr[0][(g - 2) * 4 + t] =
                            *(const ull*)(bb + ((g - 2) * 4 + t) * 8 * PITCH + (ks + 2) * 2);
                }
                #pragma unroll
                for (int ii = g * 2; ii < g * 2 + 2; ii++)
                    #pragma unroll
                    for (int jj = 0; jj < 8; jj++)
                        ffma2(acc[ii][jj], afr[1][ii], bfr[1][jj]);
            }
        }

        // ---- epilogue: exact scores, per-vector argmin (lowest-s ties) ----
        #pragma unroll
        for (int ii = 0; ii < 8; ii++) {
            const int v = 4 * ii + lv;
            const float vn = vns[v];
            ull bk = ~0ull;
            #pragma unroll
            for (int jj = 0; jj < 8; jj++) {
                float lo = __uint_as_float((unsigned)(acc[ii][jj] & 0xffffffffull));
                float hi = __uint_as_float((unsigned)(acc[ii][jj] >> 32));
                float dot = __fadd_rn(lo, hi);
                float d = __fadd_rn(__fmaf_rn(-2.0f, dot, vn), cnr[jj]);
                ull key = ((ull)fenc(d) << 32) | (unsigned)(wbase + lc + 8 * jj);
                bk = key < bk ? key : bk;
            }
            #pragma unroll
            for (int m = 1; m <= 4; m <<= 1) {
                ull o = __shfl_xor_sync(0xffffffffu, bk, m);
                bk = o < bk ? o : bk;
            }
            if (lc == 0) kbuf[v * 8 + wid] = bk;
        }
        __syncthreads();   // kbuf complete

        // ---- cross-warp merge; z, err ----
        const long i0 = (long)tile * TILE;
        if (tid < TILE) {
            ull bk = kbuf[tid * 8];
            #pragma unroll
            for (int w = 1; w < NWARP; w++) {
                ull k = kbuf[tid * 8 + w];
                bk = k < bk ? k : bk;
            }
            float d = fdec((unsigned)(bk >> 32));
            int z = (int)(bk & 0xffffffffull);
            zr[tid] = z;
            out_z[i0 + tid] = (float)z;
            rd[tid] = fmaxf(d, 0.0f);
        }
        __syncthreads();   // zr/rd visible

        // ---- gather vecs_hat = codebook[z] from smem; per-tile loss sum ----
        #pragma unroll
        for (int r = 0; r < 2; r++) {
            int n = r * NT + tid;
            int row = n >> 4, q = n & 15;
            float4 v = *(const float4*)(cbs + (long)zr[row] * PITCH + q * 4);
            *(float4*)(out + (i0 + row) * KDIM + q * 4) = v;
        }
        if (wid == 0) {
            float s = rd[lane];
            #pragma unroll
            for (int o = 16; o > 0; o >>= 1) s += __shfl_down_sync(0xffffffffu, s, o);
            if (lane == 0) g_tilesum[tile] = s;
        }
        buf ^= 1;
        __syncthreads();
    }

    // ---- last CTA: fixed-order loss reduction ----
    if (tid < 32) {
        unsigned t = 0xffffffffu;
        if (tid == 0) { __threadfence(); t = atomicAdd(&g_ticket, 1u); }
        t = __shfl_sync(0xffffffffu, t, 0);
        if (t == (unsigned)(nctas - 1)) {
            __threadfence();
            double s = 0.0;
            for (int j = 0; j < NTILES / 32; j++)
                s += (double)__ldcg(&g_tilesum[lane * (NTILES / 32) + j]);
            #pragma unroll
            for (int o = 16; o > 0; o >>= 1) s += __shfl_down_sync(0xffffffffu, s, o);
            if (lane == 0) {
                float mean = (float)(s / (double)N);
                long base = (long)N * KDIM + N;
                out[base]     = mean;   // l_commit
                out[base + 1] = mean;   // l_codebook (identical forward value)
                g_ticket = 0;
            }
        }
    }
}

extern "C" void kernel_launch(void* const* d_in, const int* in_sizes, int n_in,
                              void* d_out, int out_size) {
    const float* vecs = (const float*)d_in[0];
    const float* cb   = (const float*)d_in[1];
    float* out = (float*)d_out;

    int N = in_sizes[0] / KDIM;          // 65536
    int ntiles = N / TILE;               // 2048

    cudaFuncSetAttribute(vq_main, cudaFuncAttributeMaxDynamicSharedMemorySize, SMEM_TOTAL);
    vq_main<<<GRID, NT, SMEM_TOTAL>>>(vecs, cb, out, N, ntiles, GRID);
}